// round 11
// baseline (speedup 1.0000x reference)
#include <cuda_runtime.h>
#include <cuda_bf16.h>
#include <math.h>
#include <stdint.h>

#define BB 64
#define TT 20
#define EE 512
#define VV 32000
#define G4 2048   // 4*EE
#define NSTEP (TT - 1)

// ---------------- scratch (no allocations allowed) ----------------
__device__ float g_h[BB * EE];
__device__ float g_c[BB * EE];
__device__ float g_xgates[NSTEP * BB * G4];      // [(t-1)*64+b][4E]
__device__ unsigned g_bars[64];                  // grid-barrier slots (zeroed per call)
__device__ __nv_bfloat16 g_Ehi[TT * BB * EE];    // emb split [t*64+b][e]
__device__ __nv_bfloat16 g_Elo[TT * BB * EE];
__device__ __nv_bfloat16 g_Shi[BB * TT * EE];    // seq split [b*20+t][e] (proj A operand)
__device__ __nv_bfloat16 g_Slo[BB * TT * EE];
__device__ __nv_bfloat16 g_WoutHi[(size_t)VV * EE];
__device__ __nv_bfloat16 g_WoutLo[(size_t)VV * EE];
__device__ __nv_bfloat16 g_WihHi[G4 * EE];
__device__ __nv_bfloat16 g_WihLo[G4 * EE];

// ================= helpers =================
__device__ __forceinline__ uint32_t smem_u32(const void* p) {
    uint32_t a;
    asm("{ .reg .u64 t; cvta.to.shared.u64 t, %1; cvt.u32.u64 %0, t; }" : "=r"(a) : "l"(p));
    return a;
}
__device__ __forceinline__ void bf16_split(float v, __nv_bfloat16& h, __nv_bfloat16& l) {
    h = __float2bfloat16(v);
    l = __float2bfloat16(v - __bfloat162float(h));
}

#define LDSM4(r, a)                                                            \
    asm volatile("ldmatrix.sync.aligned.m8n8.x4.shared.b16 {%0,%1,%2,%3}, [%4];" \
        : "=r"((r)[0]), "=r"((r)[1]), "=r"((r)[2]), "=r"((r)[3]) : "r"(a))
#define LDSM2(r, a)                                                            \
    asm volatile("ldmatrix.sync.aligned.m8n8.x2.shared.b16 {%0,%1}, [%2];"     \
        : "=r"((r)[0]), "=r"((r)[1]) : "r"(a))
#define MMA_BF16(acc, a, b)                                                    \
    asm volatile("mma.sync.aligned.m16n8k16.row.col.f32.bf16.bf16.f32 "        \
        "{%0,%1,%2,%3}, {%4,%5,%6,%7}, {%8,%9}, {%0,%1,%2,%3};"                \
        : "+f"((acc)[0]), "+f"((acc)[1]), "+f"((acc)[2]), "+f"((acc)[3])       \
        : "r"((a)[0]), "r"((a)[1]), "r"((a)[2]), "r"((a)[3]),                  \
          "r"((b)[0]), "r"((b)[1]))
#define CP_ASYNC16(sp, gp)                                                     \
    asm volatile("cp.async.cg.shared.global [%0], [%1], 16;" :: "r"(sp), "l"(gp))

// ================= HMMA bf16-split GEMM =================
// CTA tile 128(M) x 256(N), 8 warps in 2x4 grid, warp tile 64x64.
// C = Ahi*Bhi + Ahi*Blo + Alo*Bhi ; A [*,512] row-major, B [N,512] row-major.
// Inner loop: B-fragment double-buffering (ldsm for ni+1 before MMAs of ni)
// and product-major MMA order (same-acc reuse distance 4).
#define BK 32
#define SRW 80                   // smem row stride bytes (64B data + 16B pad)
#define A_OP (128 * SRW)         // 10240 B per A operand tile
#define B_OP (256 * SRW)         // 20480 B per B operand tile
#define STAGEB (2 * A_OP + 2 * B_OP)  // 61440
#define SMEMB (2 * STAGEB)            // 122880

__global__ __launch_bounds__(256, 1) void hmma_gemm_kernel(
        const __nv_bfloat16* __restrict__ Ahi, const __nv_bfloat16* __restrict__ Alo,
        const __nv_bfloat16* __restrict__ Bhi, const __nv_bfloat16* __restrict__ Blo,
        float* __restrict__ C, int ldc,
        const float* __restrict__ bias1, const float* __restrict__ bias2, int mrows) {
    extern __shared__ char smem[];
    uint32_t sb = smem_u32(smem);
    int tid = threadIdx.x, lane = tid & 31, wid = tid >> 5;
    int wm = (wid & 1) * 64;        // warp M offset in tile
    int wn = (wid >> 1) * 64;       // warp N offset in tile
    int m0 = blockIdx.x * 128;
    int n0 = blockIdx.y * 256;

    float acc[4][8][4];
#pragma unroll
    for (int i = 0; i < 4; i++)
#pragma unroll
        for (int j = 0; j < 8; j++)
#pragma unroll
            for (int k = 0; k < 4; k++) acc[i][j][k] = 0.f;

    // ---- async stage loader: 3072 16B units (A hi/lo 1024 + B hi/lo 2048) ----
#define LOAD_CHUNK(kc, buf)                                                          \
    do {                                                                             \
        _Pragma("unroll")                                                            \
        for (int i_ = 0; i_ < 12; i_++) {                                            \
            int u_ = tid + i_ * 256;                                                 \
            const __nv_bfloat16* src_;                                               \
            uint32_t sp_;                                                            \
            int grow_, c_;                                                           \
            if (u_ < 1024) {                  /* A tiles */                           \
                int op_ = u_ >> 9;                                                   \
                int q_ = u_ & 511;                                                   \
                int r_ = q_ >> 2;                                                    \
                c_ = q_ & 3;                                                         \
                src_ = op_ ? Alo : Ahi;                                              \
                grow_ = m0 + r_;                                                     \
                sp_ = sb + (buf) * STAGEB + op_ * A_OP + r_ * SRW + c_ * 16;         \
            } else {                          /* B tiles */                          \
                int v_ = u_ - 1024;                                                  \
                int op_ = v_ >> 10;                                                  \
                int q_ = v_ & 1023;                                                  \
                int r_ = q_ >> 2;                                                    \
                c_ = q_ & 3;                                                         \
                src_ = op_ ? Blo : Bhi;                                              \
                grow_ = n0 + r_;                                                     \
                sp_ = sb + (buf) * STAGEB + 2 * A_OP + op_ * B_OP + r_ * SRW + c_ * 16; \
            }                                                                        \
            const void* gp_ = src_ + (size_t)grow_ * EE + (kc) * BK + c_ * 8;        \
            CP_ASYNC16(sp_, gp_);                                                    \
        }                                                                            \
        asm volatile("cp.async.commit_group;");                                      \
    } while (0)

    LOAD_CHUNK(0, 0);

    for (int kc = 0; kc < 16; kc++) {
        int buf = kc & 1;
        if (kc < 15) {
            LOAD_CHUNK(kc + 1, buf ^ 1);
            asm volatile("cp.async.wait_group 1;");
        } else {
            asm volatile("cp.async.wait_group 0;");
        }
        __syncthreads();

        uint32_t base = sb + buf * STAGEB;
#pragma unroll
        for (int ks = 0; ks < 2; ks++) {
            int kk = ks * 32;   // byte offset of k16 step (16 bf16 = 32B)
            uint32_t ah[4][4], al[4][4];
#pragma unroll
            for (int mi = 0; mi < 4; mi++) {
                uint32_t ra = base + (uint32_t)(wm + mi * 16 + (lane & 15)) * SRW
                            + kk + ((lane >> 4) << 4);
                LDSM4(ah[mi], ra);
                LDSM4(al[mi], ra + A_OP);
            }
            // B fragments: double-buffered over ni (prefetch ni+1 before MMAs of ni)
            uint32_t bh[2][2], bl[2][2];
            uint32_t rb0 = base + 2 * A_OP
                         + (uint32_t)(wn + (lane & 7)) * SRW
                         + kk + (((lane >> 3) & 1) << 4);
            LDSM2(bh[0], rb0);
            LDSM2(bl[0], rb0 + B_OP);
#pragma unroll
            for (int ni = 0; ni < 8; ni++) {
                int cur = ni & 1, nxt = cur ^ 1;
                if (ni < 7) {
                    uint32_t rb = base + 2 * A_OP
                                + (uint32_t)(wn + (ni + 1) * 8 + (lane & 7)) * SRW
                                + kk + (((lane >> 3) & 1) << 4);
                    LDSM2(bh[nxt], rb);
                    LDSM2(bl[nxt], rb + B_OP);
                }
                // product-major: same-acc reuse distance = 4 MMAs
#pragma unroll
                for (int mi = 0; mi < 4; mi++) MMA_BF16(acc[mi][ni], ah[mi], bh[cur]);
#pragma unroll
                for (int mi = 0; mi < 4; mi++) MMA_BF16(acc[mi][ni], ah[mi], bl[cur]);
#pragma unroll
                for (int mi = 0; mi < 4; mi++) MMA_BF16(acc[mi][ni], al[mi], bh[cur]);
            }
        }
        __syncthreads();
    }

    // ---- epilogue ----
#pragma unroll
    for (int ni = 0; ni < 8; ni++) {
        int c0 = n0 + wn + ni * 8 + (lane & 3) * 2;
        float b0 = bias1[c0], b1 = bias1[c0 + 1];
        if (bias2) { b0 += bias2[c0]; b1 += bias2[c0 + 1]; }
#pragma unroll
        for (int mi = 0; mi < 4; mi++) {
            int r0 = m0 + wm + mi * 16 + (lane >> 2);
            float* p = C + (size_t)r0 * ldc + c0;
            if (r0 < mrows) {
                float2 v = make_float2(acc[mi][ni][0] + b0, acc[mi][ni][1] + b1);
                *(float2*)p = v;
            }
            if (r0 + 8 < mrows) {
                float2 v = make_float2(acc[mi][ni][2] + b0, acc[mi][ni][3] + b1);
                *(float2*)(p + (size_t)8 * ldc) = v;
            }
        }
    }
}

// ================= fp32 -> (bf16 hi, bf16 lo) split =================
__global__ void split_kernel(const float* __restrict__ src,
                             __nv_bfloat16* __restrict__ hi,
                             __nv_bfloat16* __restrict__ lo, int n4) {
    int i = blockIdx.x * blockDim.x + threadIdx.x;
    if (i >= n4) return;
    float4 v = ((const float4*)src)[i];
    __nv_bfloat16 h0, h1, h2, h3, l0, l1, l2, l3;
    bf16_split(v.x, h0, l0); bf16_split(v.y, h1, l1);
    bf16_split(v.z, h2, l2); bf16_split(v.w, h3, l3);
    ((__nv_bfloat162*)hi)[2 * i + 0] = __halves2bfloat162(h0, h1);
    ((__nv_bfloat162*)hi)[2 * i + 1] = __halves2bfloat162(h2, h3);
    ((__nv_bfloat162*)lo)[2 * i + 0] = __halves2bfloat162(l0, l1);
    ((__nv_bfloat162*)lo)[2 * i + 1] = __halves2bfloat162(l2, l3);
}

// ================= embedding gather: split emb; seq row 0 =================
__global__ void gather_kernel(const int* __restrict__ captions,
                              const float* __restrict__ W_emb) {
    int idx = blockIdx.x * blockDim.x + threadIdx.x;
    if (idx >= TT * BB * EE) return;
    int e = idx % EE;
    int b = (idx / EE) % BB;
    int t = idx / (EE * BB);
    float v = W_emb[(size_t)captions[b * TT + t] * EE + e];
    __nv_bfloat16 h, l;
    bf16_split(v, h, l);
    g_Ehi[idx] = h;
    g_Elo[idx] = l;
    if (t == 0) {                               // seq[:,0] = emb[:,0]
        size_t s = ((size_t)b * TT) * EE + e;
        g_Shi[s] = h;
        g_Slo[s] = l;
    }
}

// ================= h=0, c=features, barrier slots = 0 =================
__global__ void init_state_kernel(const float* __restrict__ features) {
    int idx = blockIdx.x * blockDim.x + threadIdx.x;
    if (idx < BB * EE) { g_h[idx] = 0.f; g_c[idx] = features[idx]; }
    if (idx < 64) g_bars[idx] = 0u;
}

// ================= persistent LSTM: all 19 steps in one kernel =================
__device__ __forceinline__ void gridbar(int slot) {
    __syncthreads();
    __threadfence();
    if (threadIdx.x == 0) {
        atomicAdd(&g_bars[slot], 1u);
        while (*(volatile unsigned*)&g_bars[slot] < 128u) {}
    }
    __syncthreads();
    __threadfence();
}

__global__ __launch_bounds__(256) void lstm_persist_kernel(const float* __restrict__ W_hh) {
    __shared__ float Xs[64][36];
    __shared__ float Ws[64][36];
    int blk = blockIdx.x;
    int tid = threadIdx.x;
    int n0 = (blk & 31) * 64;
    int koff = (blk >> 5) * 128;
    int tx = tid & 15, ty = tid >> 4;

    for (int t = 1; t < TT; t++) {
        if (t > 1) {
            // ---- phase A: gates[(t-1)] += h @ W_hh^T (64x64 x K128 slice) ----
            float acc[4][4] = {};
            for (int kc = 0; kc < 128; kc += 32) {
#pragma unroll
                for (int i = 0; i < 2; i++) {
                    int q = tid + i * 256;
                    int r = q >> 3;
                    int kk = (q & 7) << 2;
                    *(float4*)(&Xs[r][kk]) =
                        *(const float4*)(g_h + (size_t)r * EE + koff + kc + kk);
                    *(float4*)(&Ws[r][kk]) =
                        *(const float4*)(W_hh + (size_t)(n0 + r) * EE + koff + kc + kk);
                }
                __syncthreads();
#pragma unroll
                for (int k4 = 0; k4 < 8; k4++) {
                    float4 xr[4], wr[4];
#pragma unroll
                    for (int i = 0; i < 4; i++) xr[i] = *(const float4*)(&Xs[ty * 4 + i][k4 * 4]);
#pragma unroll
                    for (int j = 0; j < 4; j++) wr[j] = *(const float4*)(&Ws[tx * 4 + j][k4 * 4]);
#pragma unroll
                    for (int i = 0; i < 4; i++)
#pragma unroll
                        for (int j = 0; j < 4; j++)
                            acc[i][j] += xr[i].x * wr[j].x + xr[i].y * wr[j].y
                                       + xr[i].z * wr[j].z + xr[i].w * wr[j].w;
                }
                __syncthreads();
            }
#pragma unroll
            for (int i = 0; i < 4; i++)
#pragma unroll
                for (int j = 0; j < 4; j++)
                    atomicAdd(&g_xgates[((size_t)(t - 1) * BB + ty * 4 + i) * G4
                                        + n0 + tx * 4 + j],
                              acc[i][j]);

            gridbar(2 * (t - 1));
        }

        // ---- phase B: pointwise (one element per thread) ----
        {
            int idx = blk * 256 + tid;          // 0..32767
            int bb = idx >> 9, n = idx & 511;
            const float* gp = g_xgates + ((size_t)(t - 1) * BB + bb) * G4 + n;
            float gi = gp[0];
            float gf = gp[EE];
            float gg = gp[2 * EE];
            float go = gp[3 * EE];
            float iv = 1.f / (1.f + expf(-gi));
            float fv = 1.f / (1.f + expf(-gf));
            float gv = tanhf(gg);
            float ov = 1.f / (1.f + expf(-go));
            float c = fv * g_c[idx] + iv * gv;
            g_c[idx] = c;
            float h = ov * tanhf(c);
            g_h[idx] = h;
            __nv_bfloat16 hh, hl;
            bf16_split(h, hh, hl);
            size_t s = ((size_t)bb * TT + t) * EE + n;
            g_Shi[s] = hh;
            g_Slo[s] = hl;
        }

        if (t < TT - 1) gridbar(2 * (t - 1) + 1);
    }
}

// ================= launch =================
extern "C" void kernel_launch(void* const* d_in, const int* in_sizes, int n_in,
                              void* d_out, int out_size) {
    const float* features = (const float*)d_in[0];
    const int*   captions = (const int*)d_in[1];
    const float* W_emb    = (const float*)d_in[2];
    const float* W_out    = (const float*)d_in[3];
    const float* b_out    = (const float*)d_in[4];
    const float* W_ih     = (const float*)d_in[5];
    const float* W_hh     = (const float*)d_in[6];
    const float* b_ih     = (const float*)d_in[7];
    const float* b_hh     = (const float*)d_in[8];
    float* out = (float*)d_out;

    cudaFuncSetAttribute(hmma_gemm_kernel, cudaFuncAttributeMaxDynamicSharedMemorySize, SMEMB);

    void *pEhi, *pElo, *pShi, *pSlo, *pWoH, *pWoL, *pWiH, *pWiL, *pXg;
    cudaGetSymbolAddress(&pEhi, g_Ehi);
    cudaGetSymbolAddress(&pElo, g_Elo);
    cudaGetSymbolAddress(&pShi, g_Shi);
    cudaGetSymbolAddress(&pSlo, g_Slo);
    cudaGetSymbolAddress(&pWoH, g_WoutHi);
    cudaGetSymbolAddress(&pWoL, g_WoutLo);
    cudaGetSymbolAddress(&pWiH, g_WihHi);
    cudaGetSymbolAddress(&pWiL, g_WihLo);
    cudaGetSymbolAddress(&pXg, g_xgates);

    gather_kernel<<<(TT * BB * EE + 255) / 256, 256>>>(captions, W_emb);
    init_state_kernel<<<(BB * EE + 255) / 256, 256>>>(features);

    // x-part of all LSTM steps: xgates = emb @ W_ih^T + b_ih + b_hh  (tensor cores)
    split_kernel<<<(G4 * EE / 4 + 255) / 256, 256>>>(W_ih,
        (__nv_bfloat16*)pWiH, (__nv_bfloat16*)pWiL, G4 * EE / 4);
    hmma_gemm_kernel<<<dim3((NSTEP * BB + 127) / 128, G4 / 256), 256, SMEMB>>>(
        (const __nv_bfloat16*)pEhi, (const __nv_bfloat16*)pElo,
        (const __nv_bfloat16*)pWiH, (const __nv_bfloat16*)pWiL,
        (float*)pXg, G4, b_ih, b_hh, NSTEP * BB);

    // W_out split (independent; cheap)
    split_kernel<<<((int)((size_t)VV * EE / 4) + 255) / 256, 256>>>(W_out,
        (__nv_bfloat16*)pWoH, (__nv_bfloat16*)pWoL, (int)((size_t)VV * EE / 4));

    // serial LSTM (recurrent half), one persistent kernel
    lstm_persist_kernel<<<128, 256>>>(W_hh);

    // projection: out = seq @ W_out^T + b_out  (tensor cores)
    hmma_gemm_kernel<<<dim3((TT * BB) / 128, VV / 256), 256, SMEMB>>>(
        (const __nv_bfloat16*)pShi, (const __nv_bfloat16*)pSlo,
        (const __nv_bfloat16*)pWoH, (const __nv_bfloat16*)pWoL,
        out, VV, b_out, nullptr, TT * BB);
}

// round 12
// speedup vs baseline: 1.1510x; 1.1510x over previous
#include <cuda_runtime.h>
#include <cuda_bf16.h>
#include <math.h>
#include <stdint.h>

#define BB 64
#define TT 20
#define EE 512
#define VV 32000
#define G4 2048   // 4*EE
#define NSTEP (TT - 1)

// ---------------- scratch (no allocations allowed) ----------------
__device__ float g_h[BB * EE];
__device__ float g_c[BB * EE];
__device__ float g_seq[BB * TT * EE];            // fp32 [b*20+t][e] (proj A operand)
__device__ float g_xgates[NSTEP * BB * G4];      // [(t-1)*64+b][4E]
__device__ unsigned g_bars[64];                  // grid-barrier slots (zeroed per call)
__device__ __nv_bfloat16 g_Ehi[TT * BB * EE];    // emb split [t*64+b][e]
__device__ __nv_bfloat16 g_Elo[TT * BB * EE];
__device__ __nv_bfloat16 g_WihHi[G4 * EE];
__device__ __nv_bfloat16 g_WihLo[G4 * EE];

// ================= helpers =================
__device__ __forceinline__ uint32_t smem_u32(const void* p) {
    uint32_t a;
    asm("{ .reg .u64 t; cvta.to.shared.u64 t, %1; cvt.u32.u64 %0, t; }" : "=r"(a) : "l"(p));
    return a;
}
__device__ __forceinline__ void bf16_split(float v, __nv_bfloat16& h, __nv_bfloat16& l) {
    h = __float2bfloat16(v);
    l = __float2bfloat16(v - __bfloat162float(h));
}

#define LDSM4(r, a)                                                            \
    asm volatile("ldmatrix.sync.aligned.m8n8.x4.shared.b16 {%0,%1,%2,%3}, [%4];" \
        : "=r"((r)[0]), "=r"((r)[1]), "=r"((r)[2]), "=r"((r)[3]) : "r"(a))
#define LDSM2(r, a)                                                            \
    asm volatile("ldmatrix.sync.aligned.m8n8.x2.shared.b16 {%0,%1}, [%2];"     \
        : "=r"((r)[0]), "=r"((r)[1]) : "r"(a))
#define MMA_BF16(acc, a, b)                                                    \
    asm volatile("mma.sync.aligned.m16n8k16.row.col.f32.bf16.bf16.f32 "        \
        "{%0,%1,%2,%3}, {%4,%5,%6,%7}, {%8,%9}, {%0,%1,%2,%3};"                \
        : "+f"((acc)[0]), "+f"((acc)[1]), "+f"((acc)[2]), "+f"((acc)[3])       \
        : "r"((a)[0]), "r"((a)[1]), "r"((a)[2]), "r"((a)[3]),                  \
          "r"((b)[0]), "r"((b)[1]))
#define MMA_TF32(acc, a, b)                                                    \
    asm volatile("mma.sync.aligned.m16n8k8.row.col.f32.tf32.tf32.f32 "         \
        "{%0,%1,%2,%3}, {%4,%5,%6,%7}, {%8,%9}, {%0,%1,%2,%3};"                \
        : "+f"((acc)[0]), "+f"((acc)[1]), "+f"((acc)[2]), "+f"((acc)[3])       \
        : "r"((a)[0]), "r"((a)[1]), "r"((a)[2]), "r"((a)[3]),                  \
          "r"((b)[0]), "r"((b)[1]))
#define CVT_TF32(o, f) asm("cvt.rna.tf32.f32 %0, %1;" : "=r"(o) : "f"(f))
#define LDS32(o, a) asm volatile("ld.shared.f32 %0, [%1];" : "=f"(o) : "r"(a))
#define CP_ASYNC16(sp, gp)                                                     \
    asm volatile("cp.async.cg.shared.global [%0], [%1], 16;" :: "r"(sp), "l"(gp))

// ================= bf16-split HMMA GEMM (LSTM x-gates only) =================
// CTA tile 128(M) x 256(N), 8 warps 2x4, warp tile 64x64. K=512.
#define BK 32
#define SRW 80
#define A_OP (128 * SRW)
#define B_OP (256 * SRW)
#define STAGEB (2 * A_OP + 2 * B_OP)  // 61440
#define SMEMB (2 * STAGEB)            // 122880

__global__ __launch_bounds__(256, 1) void hmma_gemm_kernel(
        const __nv_bfloat16* __restrict__ Ahi, const __nv_bfloat16* __restrict__ Alo,
        const __nv_bfloat16* __restrict__ Bhi, const __nv_bfloat16* __restrict__ Blo,
        float* __restrict__ C, int ldc,
        const float* __restrict__ bias1, const float* __restrict__ bias2, int mrows) {
    extern __shared__ char smem[];
    uint32_t sb = smem_u32(smem);
    int tid = threadIdx.x, lane = tid & 31, wid = tid >> 5;
    int wm = (wid & 1) * 64;
    int wn = (wid >> 1) * 64;
    int m0 = blockIdx.x * 128;
    int n0 = blockIdx.y * 256;

    float acc[4][8][4];
#pragma unroll
    for (int i = 0; i < 4; i++)
#pragma unroll
        for (int j = 0; j < 8; j++)
#pragma unroll
            for (int k = 0; k < 4; k++) acc[i][j][k] = 0.f;

#define LOAD_CHUNK(kc, buf)                                                          \
    do {                                                                             \
        _Pragma("unroll")                                                            \
        for (int i_ = 0; i_ < 12; i_++) {                                            \
            int u_ = tid + i_ * 256;                                                 \
            const __nv_bfloat16* src_;                                               \
            uint32_t sp_;                                                            \
            int grow_, c_;                                                           \
            if (u_ < 1024) {                                                         \
                int op_ = u_ >> 9;                                                   \
                int q_ = u_ & 511;                                                   \
                int r_ = q_ >> 2;                                                    \
                c_ = q_ & 3;                                                         \
                src_ = op_ ? Alo : Ahi;                                              \
                grow_ = m0 + r_;                                                     \
                sp_ = sb + (buf) * STAGEB + op_ * A_OP + r_ * SRW + c_ * 16;         \
            } else {                                                                 \
                int v_ = u_ - 1024;                                                  \
                int op_ = v_ >> 10;                                                  \
                int q_ = v_ & 1023;                                                  \
                int r_ = q_ >> 2;                                                    \
                c_ = q_ & 3;                                                         \
                src_ = op_ ? Blo : Bhi;                                              \
                grow_ = n0 + r_;                                                     \
                sp_ = sb + (buf) * STAGEB + 2 * A_OP + op_ * B_OP + r_ * SRW + c_ * 16; \
            }                                                                        \
            const void* gp_ = src_ + (size_t)grow_ * EE + (kc) * BK + c_ * 8;        \
            CP_ASYNC16(sp_, gp_);                                                    \
        }                                                                            \
        asm volatile("cp.async.commit_group;");                                      \
    } while (0)

    LOAD_CHUNK(0, 0);

    for (int kc = 0; kc < 16; kc++) {
        int buf = kc & 1;
        if (kc < 15) {
            LOAD_CHUNK(kc + 1, buf ^ 1);
            asm volatile("cp.async.wait_group 1;");
        } else {
            asm volatile("cp.async.wait_group 0;");
        }
        __syncthreads();

        uint32_t base = sb + buf * STAGEB;
#pragma unroll
        for (int ks = 0; ks < 2; ks++) {
            int kk = ks * 32;
            uint32_t ah[4][4], al[4][4];
#pragma unroll
            for (int mi = 0; mi < 4; mi++) {
                uint32_t ra = base + (uint32_t)(wm + mi * 16 + (lane & 15)) * SRW
                            + kk + ((lane >> 4) << 4);
                LDSM4(ah[mi], ra);
                LDSM4(al[mi], ra + A_OP);
            }
#pragma unroll
            for (int ni = 0; ni < 8; ni++) {
                uint32_t rb = base + 2 * A_OP
                            + (uint32_t)(wn + ni * 8 + (lane & 7)) * SRW
                            + kk + (((lane >> 3) & 1) << 4);
                uint32_t bh[2], bl[2];
                LDSM2(bh, rb);
                LDSM2(bl, rb + B_OP);
#pragma unroll
                for (int mi = 0; mi < 4; mi++) MMA_BF16(acc[mi][ni], ah[mi], bh);
#pragma unroll
                for (int mi = 0; mi < 4; mi++) MMA_BF16(acc[mi][ni], ah[mi], bl);
#pragma unroll
                for (int mi = 0; mi < 4; mi++) MMA_BF16(acc[mi][ni], al[mi], bh);
            }
        }
        __syncthreads();
    }

#pragma unroll
    for (int ni = 0; ni < 8; ni++) {
        int c0 = n0 + wn + ni * 8 + (lane & 3) * 2;
        float b0 = bias1[c0], b1 = bias1[c0 + 1];
        if (bias2) { b0 += bias2[c0]; b1 += bias2[c0 + 1]; }
#pragma unroll
        for (int mi = 0; mi < 4; mi++) {
            int r0 = m0 + wm + mi * 16 + (lane >> 2);
            float* p = C + (size_t)r0 * ldc + c0;
            if (r0 < mrows) {
                float2 v = make_float2(acc[mi][ni][0] + b0, acc[mi][ni][1] + b1);
                *(float2*)p = v;
            }
            if (r0 + 8 < mrows) {
                float2 v = make_float2(acc[mi][ni][2] + b0, acc[mi][ni][3] + b1);
                *(float2*)(p + (size_t)8 * ldc) = v;
            }
        }
    }
}

// ================= TF32 GEMM (projection) =================
// C[1280,32000] = seq(fp32) @ W_out^T(fp32) + b_out, tf32 single product.
// CTA tile 128(M) x 256(N), 8 warps 2x4, warp tile 64x64. K=512, BK=32 floats.
// smem row stride 144B -> bank = (4*row + col) mod 32, conflict-free frags.
#define SRF 144
#define AF_OP (128 * SRF)               // 18432
#define BF_OP (256 * SRF)               // 36864
#define STF (AF_OP + BF_OP)             // 55296
#define SMF (2 * STF)                   // 110592

__global__ __launch_bounds__(256, 1) void tf32_gemm_kernel(
        const float* __restrict__ A, const float* __restrict__ B,
        float* __restrict__ C, const float* __restrict__ bias) {
    extern __shared__ char smem[];
    uint32_t sb = smem_u32(smem);
    int tid = threadIdx.x, lane = tid & 31, wid = tid >> 5;
    int wm = (wid & 1) * 64;
    int wn = (wid >> 1) * 64;
    int m0 = blockIdx.x * 128;
    int n0 = blockIdx.y * 256;

    float acc[4][8][4];
#pragma unroll
    for (int i = 0; i < 4; i++)
#pragma unroll
        for (int j = 0; j < 8; j++)
#pragma unroll
            for (int k = 0; k < 4; k++) acc[i][j][k] = 0.f;

    // stage: A 128 rows x 32 floats, B 256 rows x 32 floats; 3072 16B units
#define LOAD_F(kc, buf)                                                              \
    do {                                                                             \
        _Pragma("unroll")                                                            \
        for (int i_ = 0; i_ < 12; i_++) {                                            \
            int u_ = tid + i_ * 256;                                                 \
            const float* src_;                                                       \
            uint32_t sp_;                                                            \
            int grow_, c_;                                                           \
            if (u_ < 1024) {                                                         \
                int r_ = u_ >> 3;                                                    \
                c_ = u_ & 7;                                                         \
                src_ = A; grow_ = m0 + r_;                                           \
                sp_ = sb + (buf) * STF + r_ * SRF + c_ * 16;                         \
            } else {                                                                 \
                int v_ = u_ - 1024;                                                  \
                int r_ = v_ >> 3;                                                    \
                c_ = v_ & 7;                                                         \
                src_ = B; grow_ = n0 + r_;                                           \
                sp_ = sb + (buf) * STF + AF_OP + r_ * SRF + c_ * 16;                 \
            }                                                                        \
            const void* gp_ = src_ + (size_t)grow_ * EE + (kc) * 32 + c_ * 4;        \
            CP_ASYNC16(sp_, gp_);                                                    \
        }                                                                            \
        asm volatile("cp.async.commit_group;");                                      \
    } while (0)

    LOAD_F(0, 0);

    for (int kc = 0; kc < 16; kc++) {
        int buf = kc & 1;
        if (kc < 15) {
            LOAD_F(kc + 1, buf ^ 1);
            asm volatile("cp.async.wait_group 1;");
        } else {
            asm volatile("cp.async.wait_group 0;");
        }
        __syncthreads();

        uint32_t base = sb + buf * STF;
#pragma unroll
        for (int ks = 0; ks < 4; ks++) {           // 4 k8 steps per 32-float chunk
            uint32_t koff = ks * 32 + (lane & 3) * 4;   // byte offset of this thread's col
            // A fragments: a0=(r,c) a1=(r+8,c) a2=(r,c+4) a3=(r+8,c+4)
            uint32_t a[4][4];
#pragma unroll
            for (int mi = 0; mi < 4; mi++) {
                uint32_t ra = base + (uint32_t)(wm + mi * 16 + (lane >> 2)) * SRF + koff;
                float f0, f1, f2, f3;
                LDS32(f0, ra);
                LDS32(f1, ra + 8 * SRF);
                LDS32(f2, ra + 16);
                LDS32(f3, ra + 8 * SRF + 16);
                CVT_TF32(a[mi][0], f0); CVT_TF32(a[mi][1], f1);
                CVT_TF32(a[mi][2], f2); CVT_TF32(a[mi][3], f3);
            }
#pragma unroll
            for (int ni = 0; ni < 8; ni++) {
                uint32_t rb = base + AF_OP
                            + (uint32_t)(wn + ni * 8 + (lane >> 2)) * SRF + koff;
                float g0, g1;
                LDS32(g0, rb);
                LDS32(g1, rb + 16);
                uint32_t b[2];
                CVT_TF32(b[0], g0); CVT_TF32(b[1], g1);
#pragma unroll
                for (int mi = 0; mi < 4; mi++) MMA_TF32(acc[mi][ni], a[mi], b);
            }
        }
        __syncthreads();
    }

    // epilogue (M=1280 exact, no guards needed)
#pragma unroll
    for (int ni = 0; ni < 8; ni++) {
        int c0 = n0 + wn + ni * 8 + (lane & 3) * 2;
        float b0 = bias[c0], b1 = bias[c0 + 1];
#pragma unroll
        for (int mi = 0; mi < 4; mi++) {
            int r0 = m0 + wm + mi * 16 + (lane >> 2);
            float* p = C + (size_t)r0 * VV + c0;
            *(float2*)p = make_float2(acc[mi][ni][0] + b0, acc[mi][ni][1] + b1);
            *(float2*)(p + (size_t)8 * VV) =
                make_float2(acc[mi][ni][2] + b0, acc[mi][ni][3] + b1);
        }
    }
}

// ================= fp32 -> (bf16 hi, bf16 lo) split =================
__global__ void split_kernel(const float* __restrict__ src,
                             __nv_bfloat16* __restrict__ hi,
                             __nv_bfloat16* __restrict__ lo, int n4) {
    int i = blockIdx.x * blockDim.x + threadIdx.x;
    if (i >= n4) return;
    float4 v = ((const float4*)src)[i];
    __nv_bfloat16 h0, h1, h2, h3, l0, l1, l2, l3;
    bf16_split(v.x, h0, l0); bf16_split(v.y, h1, l1);
    bf16_split(v.z, h2, l2); bf16_split(v.w, h3, l3);
    ((__nv_bfloat162*)hi)[2 * i + 0] = __halves2bfloat162(h0, h1);
    ((__nv_bfloat162*)hi)[2 * i + 1] = __halves2bfloat162(h2, h3);
    ((__nv_bfloat162*)lo)[2 * i + 0] = __halves2bfloat162(l0, l1);
    ((__nv_bfloat162*)lo)[2 * i + 1] = __halves2bfloat162(l2, l3);
}

// ================= embedding gather: split emb (for x-gates GEMM); seq row 0 ======
__global__ void gather_kernel(const int* __restrict__ captions,
                              const float* __restrict__ W_emb) {
    int idx = blockIdx.x * blockDim.x + threadIdx.x;
    if (idx >= TT * BB * EE) return;
    int e = idx % EE;
    int b = (idx / EE) % BB;
    int t = idx / (EE * BB);
    float v = W_emb[(size_t)captions[b * TT + t] * EE + e];
    __nv_bfloat16 h, l;
    bf16_split(v, h, l);
    g_Ehi[idx] = h;
    g_Elo[idx] = l;
    if (t == 0) g_seq[((size_t)b * TT) * EE + e] = v;   // seq[:,0] = emb[:,0]
}

// ================= h=0, c=features, barrier slots = 0 =================
__global__ void init_state_kernel(const float* __restrict__ features) {
    int idx = blockIdx.x * blockDim.x + threadIdx.x;
    if (idx < BB * EE) { g_h[idx] = 0.f; g_c[idx] = features[idx]; }
    if (idx < 64) g_bars[idx] = 0u;
}

// ================= persistent LSTM: all 19 steps in one kernel =================
__device__ __forceinline__ void gridbar(int slot) {
    __syncthreads();
    __threadfence();
    if (threadIdx.x == 0) {
        atomicAdd(&g_bars[slot], 1u);
        while (*(volatile unsigned*)&g_bars[slot] < 128u) {}
    }
    __syncthreads();
    __threadfence();
}

__global__ __launch_bounds__(256) void lstm_persist_kernel(const float* __restrict__ W_hh) {
    __shared__ float Xs[64][36];
    __shared__ float Ws[64][36];
    int blk = blockIdx.x;
    int tid = threadIdx.x;
    int n0 = (blk & 31) * 64;
    int koff = (blk >> 5) * 128;
    int tx = tid & 15, ty = tid >> 4;

    for (int t = 1; t < TT; t++) {
        if (t > 1) {
            // ---- phase A: gates[(t-1)] += h @ W_hh^T (64x64 x K128 slice) ----
            float acc[4][4] = {};
            for (int kc = 0; kc < 128; kc += 32) {
#pragma unroll
                for (int i = 0; i < 2; i++) {
                    int q = tid + i * 256;
                    int r = q >> 3;
                    int kk = (q & 7) << 2;
                    *(float4*)(&Xs[r][kk]) =
                        *(const float4*)(g_h + (size_t)r * EE + koff + kc + kk);
                    *(float4*)(&Ws[r][kk]) =
                        *(const float4*)(W_hh + (size_t)(n0 + r) * EE + koff + kc + kk);
                }
                __syncthreads();
#pragma unroll
                for (int k4 = 0; k4 < 8; k4++) {
                    float4 xr[4], wr[4];
#pragma unroll
                    for (int i = 0; i < 4; i++) xr[i] = *(const float4*)(&Xs[ty * 4 + i][k4 * 4]);
#pragma unroll
                    for (int j = 0; j < 4; j++) wr[j] = *(const float4*)(&Ws[tx * 4 + j][k4 * 4]);
#pragma unroll
                    for (int i = 0; i < 4; i++)
#pragma unroll
                        for (int j = 0; j < 4; j++)
                            acc[i][j] += xr[i].x * wr[j].x + xr[i].y * wr[j].y
                                       + xr[i].z * wr[j].z + xr[i].w * wr[j].w;
                }
                __syncthreads();
            }
#pragma unroll
            for (int i = 0; i < 4; i++)
#pragma unroll
                for (int j = 0; j < 4; j++)
                    atomicAdd(&g_xgates[((size_t)(t - 1) * BB + ty * 4 + i) * G4
                                        + n0 + tx * 4 + j],
                              acc[i][j]);

            gridbar(2 * (t - 1));
        }

        // ---- phase B: pointwise ----
        {
            int idx = blk * 256 + tid;          // 0..32767
            int bb = idx >> 9, n = idx & 511;
            const float* gp = g_xgates + ((size_t)(t - 1) * BB + bb) * G4 + n;
            float gi = gp[0];
            float gf = gp[EE];
            float gg = gp[2 * EE];
            float go = gp[3 * EE];
            float iv = 1.f / (1.f + expf(-gi));
            float fv = 1.f / (1.f + expf(-gf));
            float gv = tanhf(gg);
            float ov = 1.f / (1.f + expf(-go));
            float c = fv * g_c[idx] + iv * gv;
            g_c[idx] = c;
            float h = ov * tanhf(c);
            g_h[idx] = h;
            g_seq[((size_t)bb * TT + t) * EE + n] = h;
        }

        if (t < TT - 1) gridbar(2 * (t - 1) + 1);
    }
}

// ================= launch =================
extern "C" void kernel_launch(void* const* d_in, const int* in_sizes, int n_in,
                              void* d_out, int out_size) {
    const float* features = (const float*)d_in[0];
    const int*   captions = (const int*)d_in[1];
    const float* W_emb    = (const float*)d_in[2];
    const float* W_out    = (const float*)d_in[3];
    const float* b_out    = (const float*)d_in[4];
    const float* W_ih     = (const float*)d_in[5];
    const float* W_hh     = (const float*)d_in[6];
    const float* b_ih     = (const float*)d_in[7];
    const float* b_hh     = (const float*)d_in[8];
    float* out = (float*)d_out;

    cudaFuncSetAttribute(hmma_gemm_kernel, cudaFuncAttributeMaxDynamicSharedMemorySize, SMEMB);
    cudaFuncSetAttribute(tf32_gemm_kernel, cudaFuncAttributeMaxDynamicSharedMemorySize, SMF);

    void *pEhi, *pElo, *pWiH, *pWiL, *pXg, *pSeq;
    cudaGetSymbolAddress(&pEhi, g_Ehi);
    cudaGetSymbolAddress(&pElo, g_Elo);
    cudaGetSymbolAddress(&pWiH, g_WihHi);
    cudaGetSymbolAddress(&pWiL, g_WihLo);
    cudaGetSymbolAddress(&pXg, g_xgates);
    cudaGetSymbolAddress(&pSeq, g_seq);

    gather_kernel<<<(TT * BB * EE + 255) / 256, 256>>>(captions, W_emb);
    init_state_kernel<<<(BB * EE + 255) / 256, 256>>>(features);

    // x-part of all LSTM steps: xgates = emb @ W_ih^T + b_ih + b_hh  (bf16 split)
    split_kernel<<<(G4 * EE / 4 + 255) / 256, 256>>>(W_ih,
        (__nv_bfloat16*)pWiH, (__nv_bfloat16*)pWiL, G4 * EE / 4);
    hmma_gemm_kernel<<<dim3((NSTEP * BB + 127) / 128, G4 / 256), 256, SMEMB>>>(
        (const __nv_bfloat16*)pEhi, (const __nv_bfloat16*)pElo,
        (const __nv_bfloat16*)pWiH, (const __nv_bfloat16*)pWiL,
        (float*)pXg, G4, b_ih, b_hh, NSTEP * BB);

    // serial LSTM (recurrent half), one persistent kernel
    lstm_persist_kernel<<<128, 256>>>(W_hh);

    // projection: out = seq @ W_out^T + b_out  (tf32, fp32 operands direct)
    tf32_gemm_kernel<<<dim3((TT * BB) / 128, VV / 256), 256, SMF>>>(
        (const float*)pSeq, W_out, out, b_out);
}

// round 13
// speedup vs baseline: 1.3154x; 1.1428x over previous
#include <cuda_runtime.h>
#include <cuda_bf16.h>
#include <cuda_fp16.h>
#include <math.h>
#include <stdint.h>

#define BB 64
#define TT 20
#define EE 512
#define VV 32000
#define G4 2048   // 4*EE
#define NSTEP (TT - 1)

// ---------------- scratch (no allocations allowed) ----------------
__device__ float g_h[BB * EE];
__device__ float g_c[BB * EE];
__device__ float g_xgates[NSTEP * BB * G4];      // [(t-1)*64+b][4E]
__device__ unsigned g_bars[64];                  // grid-barrier slots (zeroed per call)
__device__ __nv_bfloat16 g_Ehi[TT * BB * EE];    // emb split [t*64+b][e]
__device__ __nv_bfloat16 g_Elo[TT * BB * EE];
__device__ __nv_bfloat16 g_WihHi[G4 * EE];
__device__ __nv_bfloat16 g_WihLo[G4 * EE];
__device__ __half g_SeqH[BB * TT * EE];          // fp16 seq [b*20+t][e] (proj A)
__device__ __half g_WoutH[(size_t)VV * EE];      // fp16 W_out (proj B)

// ================= helpers =================
__device__ __forceinline__ uint32_t smem_u32(const void* p) {
    uint32_t a;
    asm("{ .reg .u64 t; cvta.to.shared.u64 t, %1; cvt.u32.u64 %0, t; }" : "=r"(a) : "l"(p));
    return a;
}
__device__ __forceinline__ void bf16_split(float v, __nv_bfloat16& h, __nv_bfloat16& l) {
    h = __float2bfloat16(v);
    l = __float2bfloat16(v - __bfloat162float(h));
}

#define LDSM4(r, a)                                                            \
    asm volatile("ldmatrix.sync.aligned.m8n8.x4.shared.b16 {%0,%1,%2,%3}, [%4];" \
        : "=r"((r)[0]), "=r"((r)[1]), "=r"((r)[2]), "=r"((r)[3]) : "r"(a))
#define LDSM2(r, a)                                                            \
    asm volatile("ldmatrix.sync.aligned.m8n8.x2.shared.b16 {%0,%1}, [%2];"     \
        : "=r"((r)[0]), "=r"((r)[1]) : "r"(a))
#define MMA_BF16(acc, a, b)                                                    \
    asm volatile("mma.sync.aligned.m16n8k16.row.col.f32.bf16.bf16.f32 "        \
        "{%0,%1,%2,%3}, {%4,%5,%6,%7}, {%8,%9}, {%0,%1,%2,%3};"                \
        : "+f"((acc)[0]), "+f"((acc)[1]), "+f"((acc)[2]), "+f"((acc)[3])       \
        : "r"((a)[0]), "r"((a)[1]), "r"((a)[2]), "r"((a)[3]),                  \
          "r"((b)[0]), "r"((b)[1]))
#define MMA_F16(acc, a, b)                                                     \
    asm volatile("mma.sync.aligned.m16n8k16.row.col.f32.f16.f16.f32 "          \
        "{%0,%1,%2,%3}, {%4,%5,%6,%7}, {%8,%9}, {%0,%1,%2,%3};"                \
        : "+f"((acc)[0]), "+f"((acc)[1]), "+f"((acc)[2]), "+f"((acc)[3])       \
        : "r"((a)[0]), "r"((a)[1]), "r"((a)[2]), "r"((a)[3]),                  \
          "r"((b)[0]), "r"((b)[1]))
#define CP_ASYNC16(sp, gp)                                                     \
    asm volatile("cp.async.cg.shared.global [%0], [%1], 16;" :: "r"(sp), "l"(gp))

// ================= bf16-split HMMA GEMM (LSTM x-gates only) =================
// CTA tile 128(M) x 256(N), 8 warps 2x4, warp tile 64x64. K=512.
#define BK 32
#define SRW 80
#define A_OP (128 * SRW)
#define B_OP (256 * SRW)
#define STAGEB (2 * A_OP + 2 * B_OP)  // 61440
#define SMEMB (2 * STAGEB)            // 122880

__global__ __launch_bounds__(256, 1) void hmma_gemm_kernel(
        const __nv_bfloat16* __restrict__ Ahi, const __nv_bfloat16* __restrict__ Alo,
        const __nv_bfloat16* __restrict__ Bhi, const __nv_bfloat16* __restrict__ Blo,
        float* __restrict__ C, int ldc,
        const float* __restrict__ bias1, const float* __restrict__ bias2, int mrows) {
    extern __shared__ char smem[];
    uint32_t sb = smem_u32(smem);
    int tid = threadIdx.x, lane = tid & 31, wid = tid >> 5;
    int wm = (wid & 1) * 64;
    int wn = (wid >> 1) * 64;
    int m0 = blockIdx.x * 128;
    int n0 = blockIdx.y * 256;

    float acc[4][8][4];
#pragma unroll
    for (int i = 0; i < 4; i++)
#pragma unroll
        for (int j = 0; j < 8; j++)
#pragma unroll
            for (int k = 0; k < 4; k++) acc[i][j][k] = 0.f;

#define LOAD_CHUNK(kc, buf)                                                          \
    do {                                                                             \
        _Pragma("unroll")                                                            \
        for (int i_ = 0; i_ < 12; i_++) {                                            \
            int u_ = tid + i_ * 256;                                                 \
            const __nv_bfloat16* src_;                                               \
            uint32_t sp_;                                                            \
            int grow_, c_;                                                           \
            if (u_ < 1024) {                                                         \
                int op_ = u_ >> 9;                                                   \
                int q_ = u_ & 511;                                                   \
                int r_ = q_ >> 2;                                                    \
                c_ = q_ & 3;                                                         \
                src_ = op_ ? Alo : Ahi;                                              \
                grow_ = m0 + r_;                                                     \
                sp_ = sb + (buf) * STAGEB + op_ * A_OP + r_ * SRW + c_ * 16;         \
            } else {                                                                 \
                int v_ = u_ - 1024;                                                  \
                int op_ = v_ >> 10;                                                  \
                int q_ = v_ & 1023;                                                  \
                int r_ = q_ >> 2;                                                    \
                c_ = q_ & 3;                                                         \
                src_ = op_ ? Blo : Bhi;                                              \
                grow_ = n0 + r_;                                                     \
                sp_ = sb + (buf) * STAGEB + 2 * A_OP + op_ * B_OP + r_ * SRW + c_ * 16; \
            }                                                                        \
            const void* gp_ = src_ + (size_t)grow_ * EE + (kc) * BK + c_ * 8;        \
            CP_ASYNC16(sp_, gp_);                                                    \
        }                                                                            \
        asm volatile("cp.async.commit_group;");                                      \
    } while (0)

    LOAD_CHUNK(0, 0);

    for (int kc = 0; kc < 16; kc++) {
        int buf = kc & 1;
        if (kc < 15) {
            LOAD_CHUNK(kc + 1, buf ^ 1);
            asm volatile("cp.async.wait_group 1;");
        } else {
            asm volatile("cp.async.wait_group 0;");
        }
        __syncthreads();

        uint32_t base = sb + buf * STAGEB;
#pragma unroll
        for (int ks = 0; ks < 2; ks++) {
            int kk = ks * 32;
            uint32_t ah[4][4], al[4][4];
#pragma unroll
            for (int mi = 0; mi < 4; mi++) {
                uint32_t ra = base + (uint32_t)(wm + mi * 16 + (lane & 15)) * SRW
                            + kk + ((lane >> 4) << 4);
                LDSM4(ah[mi], ra);
                LDSM4(al[mi], ra + A_OP);
            }
#pragma unroll
            for (int ni = 0; ni < 8; ni++) {
                uint32_t rb = base + 2 * A_OP
                            + (uint32_t)(wn + ni * 8 + (lane & 7)) * SRW
                            + kk + (((lane >> 3) & 1) << 4);
                uint32_t bh[2], bl[2];
                LDSM2(bh, rb);
                LDSM2(bl, rb + B_OP);
#pragma unroll
                for (int mi = 0; mi < 4; mi++) MMA_BF16(acc[mi][ni], ah[mi], bh);
#pragma unroll
                for (int mi = 0; mi < 4; mi++) MMA_BF16(acc[mi][ni], ah[mi], bl);
#pragma unroll
                for (int mi = 0; mi < 4; mi++) MMA_BF16(acc[mi][ni], al[mi], bh);
            }
        }
        __syncthreads();
    }

#pragma unroll
    for (int ni = 0; ni < 8; ni++) {
        int c0 = n0 + wn + ni * 8 + (lane & 3) * 2;
        float b0 = bias1[c0], b1 = bias1[c0 + 1];
        if (bias2) { b0 += bias2[c0]; b1 += bias2[c0 + 1]; }
#pragma unroll
        for (int mi = 0; mi < 4; mi++) {
            int r0 = m0 + wm + mi * 16 + (lane >> 2);
            float* p = C + (size_t)r0 * ldc + c0;
            if (r0 < mrows) {
                float2 v = make_float2(acc[mi][ni][0] + b0, acc[mi][ni][1] + b1);
                *(float2*)p = v;
            }
            if (r0 + 8 < mrows) {
                float2 v = make_float2(acc[mi][ni][2] + b0, acc[mi][ni][3] + b1);
                *(float2*)(p + (size_t)8 * ldc) = v;
            }
        }
    }
}

// ================= fp16 single-product GEMM (projection) =================
// C[1280,32000] = seq(fp16) @ W_out^T(fp16) + b_out, fp32 accumulate.
// CTA tile 128(M) x 256(N), 8 warps 2x4, warp tile 64x64. K=512, BK=32 halfs.
#define AH_OP (128 * SRW)            // 10240
#define BH_OP (256 * SRW)            // 20480
#define STH (AH_OP + BH_OP)          // 30720
#define SMH (2 * STH)                // 61440

__global__ __launch_bounds__(256, 1) void hf16_gemm_kernel(
        const __half* __restrict__ A, const __half* __restrict__ B,
        float* __restrict__ C, const float* __restrict__ bias) {
    extern __shared__ char smem[];
    uint32_t sb = smem_u32(smem);
    int tid = threadIdx.x, lane = tid & 31, wid = tid >> 5;
    int wm = (wid & 1) * 64;
    int wn = (wid >> 1) * 64;
    int m0 = blockIdx.x * 128;
    int n0 = blockIdx.y * 256;

    float acc[4][8][4];
#pragma unroll
    for (int i = 0; i < 4; i++)
#pragma unroll
        for (int j = 0; j < 8; j++)
#pragma unroll
            for (int k = 0; k < 4; k++) acc[i][j][k] = 0.f;

    // stage: 1536 16B units (A 512 + B 1024)
#define LOAD_H(kc, buf)                                                              \
    do {                                                                             \
        _Pragma("unroll")                                                            \
        for (int i_ = 0; i_ < 6; i_++) {                                             \
            int u_ = tid + i_ * 256;                                                 \
            const __half* src_;                                                      \
            uint32_t sp_;                                                            \
            int grow_, c_;                                                           \
            if (u_ < 512) {                                                          \
                int r_ = u_ >> 2;                                                    \
                c_ = u_ & 3;                                                         \
                src_ = A; grow_ = m0 + r_;                                           \
                sp_ = sb + (buf) * STH + r_ * SRW + c_ * 16;                         \
            } else {                                                                 \
                int v_ = u_ - 512;                                                   \
                int r_ = v_ >> 2;                                                    \
                c_ = v_ & 3;                                                         \
                src_ = B; grow_ = n0 + r_;                                           \
                sp_ = sb + (buf) * STH + AH_OP + r_ * SRW + c_ * 16;                 \
            }                                                                        \
            const void* gp_ = src_ + (size_t)grow_ * EE + (kc) * BK + c_ * 8;        \
            CP_ASYNC16(sp_, gp_);                                                    \
        }                                                                            \
        asm volatile("cp.async.commit_group;");                                      \
    } while (0)

    LOAD_H(0, 0);

    for (int kc = 0; kc < 16; kc++) {
        int buf = kc & 1;
        if (kc < 15) {
            LOAD_H(kc + 1, buf ^ 1);
            asm volatile("cp.async.wait_group 1;");
        } else {
            asm volatile("cp.async.wait_group 0;");
        }
        __syncthreads();

        uint32_t base = sb + buf * STH;
#pragma unroll
        for (int ks = 0; ks < 2; ks++) {
            int kk = ks * 32;
            uint32_t a[4][4];
#pragma unroll
            for (int mi = 0; mi < 4; mi++) {
                uint32_t ra = base + (uint32_t)(wm + mi * 16 + (lane & 15)) * SRW
                            + kk + ((lane >> 4) << 4);
                LDSM4(a[mi], ra);
            }
#pragma unroll
            for (int ni = 0; ni < 8; ni++) {
                uint32_t rb = base + AH_OP
                            + (uint32_t)(wn + ni * 8 + (lane & 7)) * SRW
                            + kk + (((lane >> 3) & 1) << 4);
                uint32_t b[2];
                LDSM2(b, rb);
#pragma unroll
                for (int mi = 0; mi < 4; mi++) MMA_F16(acc[mi][ni], a[mi], b);
            }
        }
        __syncthreads();
    }

    // epilogue (M=1280, N=32000 exact — no guards)
#pragma unroll
    for (int ni = 0; ni < 8; ni++) {
        int c0 = n0 + wn + ni * 8 + (lane & 3) * 2;
        float b0 = bias[c0], b1 = bias[c0 + 1];
#pragma unroll
        for (int mi = 0; mi < 4; mi++) {
            int r0 = m0 + wm + mi * 16 + (lane >> 2);
            float* p = C + (size_t)r0 * VV + c0;
            *(float2*)p = make_float2(acc[mi][ni][0] + b0, acc[mi][ni][1] + b1);
            *(float2*)(p + (size_t)8 * VV) =
                make_float2(acc[mi][ni][2] + b0, acc[mi][ni][3] + b1);
        }
    }
}

// ================= fp32 -> fp16 convert =================
__global__ void cvt_f16_kernel(const float* __restrict__ src,
                               __half* __restrict__ dst, int n4) {
    int i = blockIdx.x * blockDim.x + threadIdx.x;
    if (i >= n4) return;
    float4 v = ((const float4*)src)[i];
    __half2 p0 = __floats2half2_rn(v.x, v.y);
    __half2 p1 = __floats2half2_rn(v.z, v.w);
    ((__half2*)dst)[2 * i + 0] = p0;
    ((__half2*)dst)[2 * i + 1] = p1;
}

// ================= fp32 -> (bf16 hi, bf16 lo) split =================
__global__ void split_kernel(const float* __restrict__ src,
                             __nv_bfloat16* __restrict__ hi,
                             __nv_bfloat16* __restrict__ lo, int n4) {
    int i = blockIdx.x * blockDim.x + threadIdx.x;
    if (i >= n4) return;
    float4 v = ((const float4*)src)[i];
    __nv_bfloat16 h0, h1, h2, h3, l0, l1, l2, l3;
    bf16_split(v.x, h0, l0); bf16_split(v.y, h1, l1);
    bf16_split(v.z, h2, l2); bf16_split(v.w, h3, l3);
    ((__nv_bfloat162*)hi)[2 * i + 0] = __halves2bfloat162(h0, h1);
    ((__nv_bfloat162*)hi)[2 * i + 1] = __halves2bfloat162(h2, h3);
    ((__nv_bfloat162*)lo)[2 * i + 0] = __halves2bfloat162(l0, l1);
    ((__nv_bfloat162*)lo)[2 * i + 1] = __halves2bfloat162(l2, l3);
}

// ================= embedding gather: split emb (x-gates); seq row 0 fp16 ======
__global__ void gather_kernel(const int* __restrict__ captions,
                              const float* __restrict__ W_emb) {
    int idx = blockIdx.x * blockDim.x + threadIdx.x;
    if (idx >= TT * BB * EE) return;
    int e = idx % EE;
    int b = (idx / EE) % BB;
    int t = idx / (EE * BB);
    float v = W_emb[(size_t)captions[b * TT + t] * EE + e];
    __nv_bfloat16 h, l;
    bf16_split(v, h, l);
    g_Ehi[idx] = h;
    g_Elo[idx] = l;
    if (t == 0) g_SeqH[((size_t)b * TT) * EE + e] = __float2half(v);
}

// ================= h=0, c=features, barrier slots = 0 =================
__global__ void init_state_kernel(const float* __restrict__ features) {
    int idx = blockIdx.x * blockDim.x + threadIdx.x;
    if (idx < BB * EE) { g_h[idx] = 0.f; g_c[idx] = features[idx]; }
    if (idx < 64) g_bars[idx] = 0u;
}

// ================= persistent LSTM: all 19 steps in one kernel =================
__device__ __forceinline__ void gridbar(int slot) {
    __syncthreads();
    __threadfence();
    if (threadIdx.x == 0) {
        atomicAdd(&g_bars[slot], 1u);
        while (*(volatile unsigned*)&g_bars[slot] < 128u) {}
    }
    __syncthreads();
    __threadfence();
}

__global__ __launch_bounds__(256) void lstm_persist_kernel(const float* __restrict__ W_hh) {
    __shared__ float Xs[64][36];
    __shared__ float Ws[64][36];
    int blk = blockIdx.x;
    int tid = threadIdx.x;
    int n0 = (blk & 31) * 64;
    int koff = (blk >> 5) * 128;
    int tx = tid & 15, ty = tid >> 4;

    for (int t = 1; t < TT; t++) {
        if (t > 1) {
            // ---- phase A: gates[(t-1)] += h @ W_hh^T (64x64 x K128 slice) ----
            float acc[4][4] = {};
            for (int kc = 0; kc < 128; kc += 32) {
#pragma unroll
                for (int i = 0; i < 2; i++) {
                    int q = tid + i * 256;
                    int r = q >> 3;
                    int kk = (q & 7) << 2;
                    *(float4*)(&Xs[r][kk]) =
                        *(const float4*)(g_h + (size_t)r * EE + koff + kc + kk);
                    *(float4*)(&Ws[r][kk]) =
                        *(const float4*)(W_hh + (size_t)(n0 + r) * EE + koff + kc + kk);
                }
                __syncthreads();
#pragma unroll
                for (int k4 = 0; k4 < 8; k4++) {
                    float4 xr[4], wr[4];
#pragma unroll
                    for (int i = 0; i < 4; i++) xr[i] = *(const float4*)(&Xs[ty * 4 + i][k4 * 4]);
#pragma unroll
                    for (int j = 0; j < 4; j++) wr[j] = *(const float4*)(&Ws[tx * 4 + j][k4 * 4]);
#pragma unroll
                    for (int i = 0; i < 4; i++)
#pragma unroll
                        for (int j = 0; j < 4; j++)
                            acc[i][j] += xr[i].x * wr[j].x + xr[i].y * wr[j].y
                                       + xr[i].z * wr[j].z + xr[i].w * wr[j].w;
                }
                __syncthreads();
            }
#pragma unroll
            for (int i = 0; i < 4; i++)
#pragma unroll
                for (int j = 0; j < 4; j++)
                    atomicAdd(&g_xgates[((size_t)(t - 1) * BB + ty * 4 + i) * G4
                                        + n0 + tx * 4 + j],
                              acc[i][j]);

            gridbar(2 * (t - 1));
        }

        // ---- phase B: pointwise ----
        {
            int idx = blk * 256 + tid;          // 0..32767
            int bb = idx >> 9, n = idx & 511;
            const float* gp = g_xgates + ((size_t)(t - 1) * BB + bb) * G4 + n;
            float gi = gp[0];
            float gf = gp[EE];
            float gg = gp[2 * EE];
            float go = gp[3 * EE];
            float iv = 1.f / (1.f + expf(-gi));
            float fv = 1.f / (1.f + expf(-gf));
            float gv = tanhf(gg);
            float ov = 1.f / (1.f + expf(-go));
            float c = fv * g_c[idx] + iv * gv;
            g_c[idx] = c;
            float h = ov * tanhf(c);
            g_h[idx] = h;
            g_SeqH[((size_t)bb * TT + t) * EE + n] = __float2half(h);
        }

        if (t < TT - 1) gridbar(2 * (t - 1) + 1);
    }
}

// ================= launch =================
extern "C" void kernel_launch(void* const* d_in, const int* in_sizes, int n_in,
                              void* d_out, int out_size) {
    const float* features = (const float*)d_in[0];
    const int*   captions = (const int*)d_in[1];
    const float* W_emb    = (const float*)d_in[2];
    const float* W_out    = (const float*)d_in[3];
    const float* b_out    = (const float*)d_in[4];
    const float* W_ih     = (const float*)d_in[5];
    const float* W_hh     = (const float*)d_in[6];
    const float* b_ih     = (const float*)d_in[7];
    const float* b_hh     = (const float*)d_in[8];
    float* out = (float*)d_out;

    cudaFuncSetAttribute(hmma_gemm_kernel, cudaFuncAttributeMaxDynamicSharedMemorySize, SMEMB);
    cudaFuncSetAttribute(hf16_gemm_kernel, cudaFuncAttributeMaxDynamicSharedMemorySize, SMH);

    void *pEhi, *pElo, *pWiH, *pWiL, *pXg, *pSeqH, *pWoH;
    cudaGetSymbolAddress(&pEhi, g_Ehi);
    cudaGetSymbolAddress(&pElo, g_Elo);
    cudaGetSymbolAddress(&pWiH, g_WihHi);
    cudaGetSymbolAddress(&pWiL, g_WihLo);
    cudaGetSymbolAddress(&pXg, g_xgates);
    cudaGetSymbolAddress(&pSeqH, g_SeqH);
    cudaGetSymbolAddress(&pWoH, g_WoutH);

    gather_kernel<<<(TT * BB * EE + 255) / 256, 256>>>(captions, W_emb);
    init_state_kernel<<<(BB * EE + 255) / 256, 256>>>(features);

    // x-part of all LSTM steps: xgates = emb @ W_ih^T + b_ih + b_hh  (bf16 split)
    split_kernel<<<(G4 * EE / 4 + 255) / 256, 256>>>(W_ih,
        (__nv_bfloat16*)pWiH, (__nv_bfloat16*)pWiL, G4 * EE / 4);
    hmma_gemm_kernel<<<dim3((NSTEP * BB + 127) / 128, G4 / 256), 256, SMEMB>>>(
        (const __nv_bfloat16*)pEhi, (const __nv_bfloat16*)pElo,
        (const __nv_bfloat16*)pWiH, (const __nv_bfloat16*)pWiL,
        (float*)pXg, G4, b_ih, b_hh, NSTEP * BB);

    // W_out -> fp16 (independent of LSTM chain)
    cvt_f16_kernel<<<((int)((size_t)VV * EE / 4) + 255) / 256, 256>>>(
        W_out, (__half*)pWoH, (int)((size_t)VV * EE / 4));

    // serial LSTM (recurrent half), one persistent kernel
    lstm_persist_kernel<<<128, 256>>>(W_hh);

    // projection: out = seq @ W_out^T + b_out  (fp16 single product)
    hf16_gemm_kernel<<<dim3((TT * BB) / 128, VV / 256), 256, SMH>>>(
        (const __half*)pSeqH, (const __half*)pWoH, out, b_out);
}

// round 14
// speedup vs baseline: 2.0257x; 1.5400x over previous
#include <cuda_runtime.h>
#include <cuda_bf16.h>
#include <cuda_fp16.h>
#include <math.h>
#include <stdint.h>

#define BB 64
#define TT 20
#define EE 512
#define VV 32000
#define G4 2048   // 4*EE
#define NSTEP (TT - 1)

// ---------------- scratch (no allocations allowed) ----------------
__device__ float g_c[BB * EE];
__device__ float g_xgates[NSTEP * BB * G4];      // [(t-1)*64+b][4E]
__device__ unsigned g_bars[64];                  // grid-barrier slots (zeroed per call)
__device__ __nv_bfloat16 g_Hhi[BB * EE];         // h split [b][e] (recurrent A operand)
__device__ __nv_bfloat16 g_Hlo[BB * EE];
__device__ __nv_bfloat16 g_Ehi[TT * BB * EE];    // emb split [t*64+b][e]
__device__ __nv_bfloat16 g_Elo[TT * BB * EE];
__device__ __nv_bfloat16 g_WihHi[G4 * EE];
__device__ __nv_bfloat16 g_WihLo[G4 * EE];
__device__ __nv_bfloat16 g_WhhHi[G4 * EE];
__device__ __nv_bfloat16 g_WhhLo[G4 * EE];
__device__ __half g_SeqH[BB * TT * EE];          // fp16 seq [b*20+t][e] (proj A)
__device__ __half g_WoutH[(size_t)VV * EE];      // fp16 W_out (proj B)

// ================= helpers =================
__device__ __forceinline__ uint32_t smem_u32(const void* p) {
    uint32_t a;
    asm("{ .reg .u64 t; cvta.to.shared.u64 t, %1; cvt.u32.u64 %0, t; }" : "=r"(a) : "l"(p));
    return a;
}
__device__ __forceinline__ void bf16_split(float v, __nv_bfloat16& h, __nv_bfloat16& l) {
    h = __float2bfloat16(v);
    l = __float2bfloat16(v - __bfloat162float(h));
}

#define LDSM4(r, a)                                                            \
    asm volatile("ldmatrix.sync.aligned.m8n8.x4.shared.b16 {%0,%1,%2,%3}, [%4];" \
        : "=r"((r)[0]), "=r"((r)[1]), "=r"((r)[2]), "=r"((r)[3]) : "r"(a))
#define LDSM2(r, a)                                                            \
    asm volatile("ldmatrix.sync.aligned.m8n8.x2.shared.b16 {%0,%1}, [%2];"     \
        : "=r"((r)[0]), "=r"((r)[1]) : "r"(a))
#define MMA_BF16(acc, a, b)                                                    \
    asm volatile("mma.sync.aligned.m16n8k16.row.col.f32.bf16.bf16.f32 "        \
        "{%0,%1,%2,%3}, {%4,%5,%6,%7}, {%8,%9}, {%0,%1,%2,%3};"                \
        : "+f"((acc)[0]), "+f"((acc)[1]), "+f"((acc)[2]), "+f"((acc)[3])       \
        : "r"((a)[0]), "r"((a)[1]), "r"((a)[2]), "r"((a)[3]),                  \
          "r"((b)[0]), "r"((b)[1]))
#define MMA_F16(acc, a, b)                                                     \
    asm volatile("mma.sync.aligned.m16n8k16.row.col.f32.f16.f16.f32 "          \
        "{%0,%1,%2,%3}, {%4,%5,%6,%7}, {%8,%9}, {%0,%1,%2,%3};"                \
        : "+f"((acc)[0]), "+f"((acc)[1]), "+f"((acc)[2]), "+f"((acc)[3])       \
        : "r"((a)[0]), "r"((a)[1]), "r"((a)[2]), "r"((a)[3]),                  \
          "r"((b)[0]), "r"((b)[1]))
#define CP_ASYNC16(sp, gp)                                                     \
    asm volatile("cp.async.cg.shared.global [%0], [%1], 16;" :: "r"(sp), "l"(gp))

// ================= bf16-split HMMA GEMM (LSTM x-gates only) =================
// CTA tile 128(M) x 256(N), 8 warps 2x4, warp tile 64x64. K=512.
#define BK 32
#define SRW 80
#define A_OP (128 * SRW)
#define B_OP (256 * SRW)
#define STAGEB (2 * A_OP + 2 * B_OP)  // 61440
#define SMEMB (2 * STAGEB)            // 122880

__global__ __launch_bounds__(256, 1) void hmma_gemm_kernel(
        const __nv_bfloat16* __restrict__ Ahi, const __nv_bfloat16* __restrict__ Alo,
        const __nv_bfloat16* __restrict__ Bhi, const __nv_bfloat16* __restrict__ Blo,
        float* __restrict__ C, int ldc,
        const float* __restrict__ bias1, const float* __restrict__ bias2, int mrows) {
    extern __shared__ char smem[];
    uint32_t sb = smem_u32(smem);
    int tid = threadIdx.x, lane = tid & 31, wid = tid >> 5;
    int wm = (wid & 1) * 64;
    int wn = (wid >> 1) * 64;
    int m0 = blockIdx.x * 128;
    int n0 = blockIdx.y * 256;

    float acc[4][8][4];
#pragma unroll
    for (int i = 0; i < 4; i++)
#pragma unroll
        for (int j = 0; j < 8; j++)
#pragma unroll
            for (int k = 0; k < 4; k++) acc[i][j][k] = 0.f;

#define LOAD_CHUNK(kc, buf)                                                          \
    do {                                                                             \
        _Pragma("unroll")                                                            \
        for (int i_ = 0; i_ < 12; i_++) {                                            \
            int u_ = tid + i_ * 256;                                                 \
            const __nv_bfloat16* src_;                                               \
            uint32_t sp_;                                                            \
            int grow_, c_;                                                           \
            if (u_ < 1024) {                                                         \
                int op_ = u_ >> 9;                                                   \
                int q_ = u_ & 511;                                                   \
                int r_ = q_ >> 2;                                                    \
                c_ = q_ & 3;                                                         \
                src_ = op_ ? Alo : Ahi;                                              \
                grow_ = m0 + r_;                                                     \
                sp_ = sb + (buf) * STAGEB + op_ * A_OP + r_ * SRW + c_ * 16;         \
            } else {                                                                 \
                int v_ = u_ - 1024;                                                  \
                int op_ = v_ >> 10;                                                  \
                int q_ = v_ & 1023;                                                  \
                int r_ = q_ >> 2;                                                    \
                c_ = q_ & 3;                                                         \
                src_ = op_ ? Blo : Bhi;                                              \
                grow_ = n0 + r_;                                                     \
                sp_ = sb + (buf) * STAGEB + 2 * A_OP + op_ * B_OP + r_ * SRW + c_ * 16; \
            }                                                                        \
            const void* gp_ = src_ + (size_t)grow_ * EE + (kc) * BK + c_ * 8;        \
            CP_ASYNC16(sp_, gp_);                                                    \
        }                                                                            \
        asm volatile("cp.async.commit_group;");                                      \
    } while (0)

    LOAD_CHUNK(0, 0);

    for (int kc = 0; kc < 16; kc++) {
        int buf = kc & 1;
        if (kc < 15) {
            LOAD_CHUNK(kc + 1, buf ^ 1);
            asm volatile("cp.async.wait_group 1;");
        } else {
            asm volatile("cp.async.wait_group 0;");
        }
        __syncthreads();

        uint32_t base = sb + buf * STAGEB;
#pragma unroll
        for (int ks = 0; ks < 2; ks++) {
            int kk = ks * 32;
            uint32_t ah[4][4], al[4][4];
#pragma unroll
            for (int mi = 0; mi < 4; mi++) {
                uint32_t ra = base + (uint32_t)(wm + mi * 16 + (lane & 15)) * SRW
                            + kk + ((lane >> 4) << 4);
                LDSM4(ah[mi], ra);
                LDSM4(al[mi], ra + A_OP);
            }
#pragma unroll
            for (int ni = 0; ni < 8; ni++) {
                uint32_t rb = base + 2 * A_OP
                            + (uint32_t)(wn + ni * 8 + (lane & 7)) * SRW
                            + kk + (((lane >> 3) & 1) << 4);
                uint32_t bh[2], bl[2];
                LDSM2(bh, rb);
                LDSM2(bl, rb + B_OP);
#pragma unroll
                for (int mi = 0; mi < 4; mi++) MMA_BF16(acc[mi][ni], ah[mi], bh);
#pragma unroll
                for (int mi = 0; mi < 4; mi++) MMA_BF16(acc[mi][ni], ah[mi], bl);
#pragma unroll
                for (int mi = 0; mi < 4; mi++) MMA_BF16(acc[mi][ni], al[mi], bh);
            }
        }
        __syncthreads();
    }

#pragma unroll
    for (int ni = 0; ni < 8; ni++) {
        int c0 = n0 + wn + ni * 8 + (lane & 3) * 2;
        float b0 = bias1[c0], b1 = bias1[c0 + 1];
        if (bias2) { b0 += bias2[c0]; b1 += bias2[c0 + 1]; }
#pragma unroll
        for (int mi = 0; mi < 4; mi++) {
            int r0 = m0 + wm + mi * 16 + (lane >> 2);
            float* p = C + (size_t)r0 * ldc + c0;
            if (r0 < mrows) {
                float2 v = make_float2(acc[mi][ni][0] + b0, acc[mi][ni][1] + b1);
                *(float2*)p = v;
            }
            if (r0 + 8 < mrows) {
                float2 v = make_float2(acc[mi][ni][2] + b0, acc[mi][ni][3] + b1);
                *(float2*)(p + (size_t)8 * ldc) = v;
            }
        }
    }
}

// ================= fp16 single-product GEMM (projection) =================
#define AH_OP (128 * SRW)            // 10240
#define BH_OP (256 * SRW)            // 20480
#define STH (AH_OP + BH_OP)          // 30720
#define SMH (2 * STH)                // 61440

__global__ __launch_bounds__(256, 1) void hf16_gemm_kernel(
        const __half* __restrict__ A, const __half* __restrict__ B,
        float* __restrict__ C, const float* __restrict__ bias) {
    extern __shared__ char smem[];
    uint32_t sb = smem_u32(smem);
    int tid = threadIdx.x, lane = tid & 31, wid = tid >> 5;
    int wm = (wid & 1) * 64;
    int wn = (wid >> 1) * 64;
    int m0 = blockIdx.x * 128;
    int n0 = blockIdx.y * 256;

    float acc[4][8][4];
#pragma unroll
    for (int i = 0; i < 4; i++)
#pragma unroll
        for (int j = 0; j < 8; j++)
#pragma unroll
            for (int k = 0; k < 4; k++) acc[i][j][k] = 0.f;

#define LOAD_H(kc, buf)                                                              \
    do {                                                                             \
        _Pragma("unroll")                                                            \
        for (int i_ = 0; i_ < 6; i_++) {                                             \
            int u_ = tid + i_ * 256;                                                 \
            const __half* src_;                                                      \
            uint32_t sp_;                                                            \
            int grow_, c_;                                                           \
            if (u_ < 512) {                                                          \
                int r_ = u_ >> 2;                                                    \
                c_ = u_ & 3;                                                         \
                src_ = A; grow_ = m0 + r_;                                           \
                sp_ = sb + (buf) * STH + r_ * SRW + c_ * 16;                         \
            } else {                                                                 \
                int v_ = u_ - 512;                                                   \
                int r_ = v_ >> 2;                                                    \
                c_ = v_ & 3;                                                         \
                src_ = B; grow_ = n0 + r_;                                           \
                sp_ = sb + (buf) * STH + AH_OP + r_ * SRW + c_ * 16;                 \
            }                                                                        \
            const void* gp_ = src_ + (size_t)grow_ * EE + (kc) * BK + c_ * 8;        \
            CP_ASYNC16(sp_, gp_);                                                    \
        }                                                                            \
        asm volatile("cp.async.commit_group;");                                      \
    } while (0)

    LOAD_H(0, 0);

    for (int kc = 0; kc < 16; kc++) {
        int buf = kc & 1;
        if (kc < 15) {
            LOAD_H(kc + 1, buf ^ 1);
            asm volatile("cp.async.wait_group 1;");
        } else {
            asm volatile("cp.async.wait_group 0;");
        }
        __syncthreads();

        uint32_t base = sb + buf * STH;
#pragma unroll
        for (int ks = 0; ks < 2; ks++) {
            int kk = ks * 32;
            uint32_t a[4][4];
#pragma unroll
            for (int mi = 0; mi < 4; mi++) {
                uint32_t ra = base + (uint32_t)(wm + mi * 16 + (lane & 15)) * SRW
                            + kk + ((lane >> 4) << 4);
                LDSM4(a[mi], ra);
            }
#pragma unroll
            for (int ni = 0; ni < 8; ni++) {
                uint32_t rb = base + AH_OP
                            + (uint32_t)(wn + ni * 8 + (lane & 7)) * SRW
                            + kk + (((lane >> 3) & 1) << 4);
                uint32_t b[2];
                LDSM2(b, rb);
#pragma unroll
                for (int mi = 0; mi < 4; mi++) MMA_F16(acc[mi][ni], a[mi], b);
            }
        }
        __syncthreads();
    }

#pragma unroll
    for (int ni = 0; ni < 8; ni++) {
        int c0 = n0 + wn + ni * 8 + (lane & 3) * 2;
        float b0 = bias[c0], b1 = bias[c0 + 1];
#pragma unroll
        for (int mi = 0; mi < 4; mi++) {
            int r0 = m0 + wm + mi * 16 + (lane >> 2);
            float* p = C + (size_t)r0 * VV + c0;
            *(float2*)p = make_float2(acc[mi][ni][0] + b0, acc[mi][ni][1] + b1);
            *(float2*)(p + (size_t)8 * VV) =
                make_float2(acc[mi][ni][2] + b0, acc[mi][ni][3] + b1);
        }
    }
}

// ================= fp32 -> fp16 convert =================
__global__ void cvt_f16_kernel(const float* __restrict__ src,
                               __half* __restrict__ dst, int n4) {
    int i = blockIdx.x * blockDim.x + threadIdx.x;
    if (i >= n4) return;
    float4 v = ((const float4*)src)[i];
    ((__half2*)dst)[2 * i + 0] = __floats2half2_rn(v.x, v.y);
    ((__half2*)dst)[2 * i + 1] = __floats2half2_rn(v.z, v.w);
}

// ================= fp32 -> (bf16 hi, bf16 lo) split =================
__global__ void split_kernel(const float* __restrict__ src,
                             __nv_bfloat16* __restrict__ hi,
                             __nv_bfloat16* __restrict__ lo, int n4) {
    int i = blockIdx.x * blockDim.x + threadIdx.x;
    if (i >= n4) return;
    float4 v = ((const float4*)src)[i];
    __nv_bfloat16 h0, h1, h2, h3, l0, l1, l2, l3;
    bf16_split(v.x, h0, l0); bf16_split(v.y, h1, l1);
    bf16_split(v.z, h2, l2); bf16_split(v.w, h3, l3);
    ((__nv_bfloat162*)hi)[2 * i + 0] = __halves2bfloat162(h0, h1);
    ((__nv_bfloat162*)hi)[2 * i + 1] = __halves2bfloat162(h2, h3);
    ((__nv_bfloat162*)lo)[2 * i + 0] = __halves2bfloat162(l0, l1);
    ((__nv_bfloat162*)lo)[2 * i + 1] = __halves2bfloat162(l2, l3);
}

// ================= embedding gather =================
__global__ void gather_kernel(const int* __restrict__ captions,
                              const float* __restrict__ W_emb) {
    int idx = blockIdx.x * blockDim.x + threadIdx.x;
    if (idx >= TT * BB * EE) return;
    int e = idx % EE;
    int b = (idx / EE) % BB;
    int t = idx / (EE * BB);
    float v = W_emb[(size_t)captions[b * TT + t] * EE + e];
    __nv_bfloat16 h, l;
    bf16_split(v, h, l);
    g_Ehi[idx] = h;
    g_Elo[idx] = l;
    if (t == 0) g_SeqH[((size_t)b * TT) * EE + e] = __float2half(v);
}

// ================= h split = 0, c = features, bars = 0 =================
__global__ void init_state_kernel(const float* __restrict__ features) {
    int idx = blockIdx.x * blockDim.x + threadIdx.x;
    if (idx < BB * EE) {
        g_c[idx] = features[idx];
        g_Hhi[idx] = __float2bfloat16(0.f);
        g_Hlo[idx] = __float2bfloat16(0.f);
    }
    if (idx < 64) g_bars[idx] = 0u;
}

// ================= persistent LSTM (HMMA recurrent GEMM) =================
// 128 CTAs x 256 thr. Per step (t>1): phase A HMMA 64x64xK128 bf16-split
// 3-product, fp32 atomics into g_xgates; barrier; phase B pointwise writes
// c, fp16 seq, and bf16 hi/lo split of h; barrier.
#define SRP 272                   // smem row stride (256B data + 16B pad)
#define P_OP (64 * SRP)           // 17408 B per operand tile
#define SMP (4 * P_OP)            // 69632: Hhi, Hlo, Whi, Wlo

__device__ __forceinline__ void gridbar(int slot) {
    __syncthreads();
    __threadfence();
    if (threadIdx.x == 0) {
        atomicAdd(&g_bars[slot], 1u);
        while (*(volatile unsigned*)&g_bars[slot] < 128u) {}
    }
    __syncthreads();
    __threadfence();
}

__global__ __launch_bounds__(256) void lstm_persist_kernel() {
    extern __shared__ char smem[];
    uint32_t sb = smem_u32(smem);
    int blk = blockIdx.x;
    int tid = threadIdx.x;
    int lane = tid & 31, wid = tid >> 5;
    int n0 = (blk & 31) * 64;
    int koff = (blk >> 5) * 128;
    int wm = (wid & 3) * 16;        // warp M offset (batch rows)
    int wn = (wid >> 2) * 32;       // warp N offset

    for (int t = 1; t < TT; t++) {
        if (t > 1) {
            // ---- phase A: load 4 operand tiles (64 rows x 128 bf16 each) ----
#pragma unroll
            for (int i = 0; i < 16; i++) {
                int u = tid + i * 256;          // 0..4095 16B units
                int op = u >> 10;               // 0=Hhi 1=Hlo 2=Whi 3=Wlo
                int q = u & 1023;
                int r = q >> 4;                 // row 0..63
                int c = q & 15;                 // 16B unit in 256B row
                const __nv_bfloat16* src =
                    (op == 0) ? g_Hhi : (op == 1) ? g_Hlo
                  : (op == 2) ? g_WhhHi : g_WhhLo;
                int grow = (op < 2) ? r : (n0 + r);
                const void* gp = src + (size_t)grow * EE + koff + c * 8;
                CP_ASYNC16(sb + op * P_OP + r * SRP + c * 16, gp);
            }
            asm volatile("cp.async.commit_group;");
            asm volatile("cp.async.wait_group 0;");
            __syncthreads();

            float acc[4][4];
#pragma unroll
            for (int i = 0; i < 4; i++)
#pragma unroll
                for (int j = 0; j < 4; j++) acc[i][j] = 0.f;

#pragma unroll
            for (int ks = 0; ks < 8; ks++) {
                int kk = ks * 32;
                uint32_t ah[4], al[4];
                uint32_t ra = sb + (uint32_t)(wm + (lane & 15)) * SRP
                            + kk + ((lane >> 4) << 4);
                LDSM4(ah, ra);
                LDSM4(al, ra + P_OP);
#pragma unroll
                for (int ni = 0; ni < 4; ni++) {
                    uint32_t rb = sb + 2 * P_OP
                                + (uint32_t)(wn + ni * 8 + (lane & 7)) * SRP
                                + kk + (((lane >> 3) & 1) << 4);
                    uint32_t bh[2], bl[2];
                    LDSM2(bh, rb);
                    LDSM2(bl, rb + P_OP);
                    MMA_BF16(acc[ni], ah, bh);
                    MMA_BF16(acc[ni], ah, bl);
                    MMA_BF16(acc[ni], al, bh);
                }
            }
            // atomically accumulate into xgates (16 values/thread)
            float* gbase = g_xgates + (size_t)(t - 1) * BB * G4;
#pragma unroll
            for (int ni = 0; ni < 4; ni++) {
                int c0 = n0 + wn + ni * 8 + (lane & 3) * 2;
                int r0 = wm + (lane >> 2);
                atomicAdd(gbase + (size_t)r0 * G4 + c0, acc[ni][0]);
                atomicAdd(gbase + (size_t)r0 * G4 + c0 + 1, acc[ni][1]);
                atomicAdd(gbase + (size_t)(r0 + 8) * G4 + c0, acc[ni][2]);
                atomicAdd(gbase + (size_t)(r0 + 8) * G4 + c0 + 1, acc[ni][3]);
            }

            gridbar(2 * (t - 1));
        }

        // ---- phase B: pointwise ----
        {
            int idx = blk * 256 + tid;          // 0..32767
            int bb = idx >> 9, n = idx & 511;
            const float* gp = g_xgates + ((size_t)(t - 1) * BB + bb) * G4 + n;
            float gi = gp[0];
            float gf = gp[EE];
            float gg = gp[2 * EE];
            float go = gp[3 * EE];
            float iv = 1.f / (1.f + expf(-gi));
            float fv = 1.f / (1.f + expf(-gf));
            float gv = tanhf(gg);
            float ov = 1.f / (1.f + expf(-go));
            float c = fv * g_c[idx] + iv * gv;
            g_c[idx] = c;
            float h = ov * tanhf(c);
            __nv_bfloat16 hh, hl;
            bf16_split(h, hh, hl);
            g_Hhi[idx] = hh;                    // idx == bb*512 + n
            g_Hlo[idx] = hl;
            g_SeqH[((size_t)bb * TT + t) * EE + n] = __float2half(h);
        }

        if (t < TT - 1) gridbar(2 * (t - 1) + 1);
    }
}

// ================= launch =================
extern "C" void kernel_launch(void* const* d_in, const int* in_sizes, int n_in,
                              void* d_out, int out_size) {
    const float* features = (const float*)d_in[0];
    const int*   captions = (const int*)d_in[1];
    const float* W_emb    = (const float*)d_in[2];
    const float* W_out    = (const float*)d_in[3];
    const float* b_out    = (const float*)d_in[4];
    const float* W_ih     = (const float*)d_in[5];
    const float* W_hh     = (const float*)d_in[6];
    const float* b_ih     = (const float*)d_in[7];
    const float* b_hh     = (const float*)d_in[8];
    float* out = (float*)d_out;

    cudaFuncSetAttribute(hmma_gemm_kernel, cudaFuncAttributeMaxDynamicSharedMemorySize, SMEMB);
    cudaFuncSetAttribute(hf16_gemm_kernel, cudaFuncAttributeMaxDynamicSharedMemorySize, SMH);
    cudaFuncSetAttribute(lstm_persist_kernel, cudaFuncAttributeMaxDynamicSharedMemorySize, SMP);

    void *pEhi, *pElo, *pWiH, *pWiL, *pWhH, *pWhL, *pXg, *pSeqH, *pWoH;
    cudaGetSymbolAddress(&pEhi, g_Ehi);
    cudaGetSymbolAddress(&pElo, g_Elo);
    cudaGetSymbolAddress(&pWiH, g_WihHi);
    cudaGetSymbolAddress(&pWiL, g_WihLo);
    cudaGetSymbolAddress(&pWhH, g_WhhHi);
    cudaGetSymbolAddress(&pWhL, g_WhhLo);
    cudaGetSymbolAddress(&pXg, g_xgates);
    cudaGetSymbolAddress(&pSeqH, g_SeqH);
    cudaGetSymbolAddress(&pWoH, g_WoutH);

    gather_kernel<<<(TT * BB * EE + 255) / 256, 256>>>(captions, W_emb);
    init_state_kernel<<<(BB * EE + 255) / 256, 256>>>(features);

    // x-part of all LSTM steps: xgates = emb @ W_ih^T + b_ih + b_hh  (bf16 split)
    split_kernel<<<(G4 * EE / 4 + 255) / 256, 256>>>(W_ih,
        (__nv_bfloat16*)pWiH, (__nv_bfloat16*)pWiL, G4 * EE / 4);
    split_kernel<<<(G4 * EE / 4 + 255) / 256, 256>>>(W_hh,
        (__nv_bfloat16*)pWhH, (__nv_bfloat16*)pWhL, G4 * EE / 4);
    hmma_gemm_kernel<<<dim3((NSTEP * BB + 127) / 128, G4 / 256), 256, SMEMB>>>(
        (const __nv_bfloat16*)pEhi, (const __nv_bfloat16*)pElo,
        (const __nv_bfloat16*)pWiH, (const __nv_bfloat16*)pWiL,
        (float*)pXg, G4, b_ih, b_hh, NSTEP * BB);

    // W_out -> fp16 (independent of LSTM chain)
    cvt_f16_kernel<<<((int)((size_t)VV * EE / 4) + 255) / 256, 256>>>(
        W_out, (__half*)pWoH, (int)((size_t)VV * EE / 4));

    // serial LSTM (recurrent half), one persistent kernel, HMMA phase A
    lstm_persist_kernel<<<128, 256, SMP>>>();

    // projection: out = seq @ W_out^T + b_out  (fp16 single product)
    hf16_gemm_kernel<<<dim3((TT * BB) / 128, VV / 256), 256, SMH>>>(
        (const __half*)pSeqH, (const __half*)pWoH, out, b_out);
}